// round 2
// baseline (speedup 1.0000x reference)
#include <cuda_runtime.h>
#include <cuda_bf16.h>
#include <cstdint>

// ============================================================================
// double-float (df64) arithmetic on the fp32 pipe (~47-bit mantissa, eps~7e-15)
// ============================================================================
struct df { float h, l; };

__device__ __forceinline__ df mkdf(float h, float l) { df r; r.h = h; r.l = l; return r; }

// quick_two_sum: requires |a| >= |b| (or a == 0)
__device__ __forceinline__ df qts(float a, float b) {
    float s = a + b;
    return mkdf(s, b - (s - a));
}
// two_sum (Knuth, unordered)
__device__ __forceinline__ df ts(float a, float b) {
    float s  = a + b;
    float bb = s - a;
    return mkdf(s, (a - (s - bb)) + (b - bb));
}
__device__ __forceinline__ df dadd(df a, df b) {
    df s = ts(a.h, b.h);
    float e = s.l + (a.l + b.l);
    return qts(s.h, e);
}
__device__ __forceinline__ df dneg(df a) { return mkdf(-a.h, -a.l); }
__device__ __forceinline__ df dsub(df a, df b) { return dadd(a, dneg(b)); }
__device__ __forceinline__ df dmul(df a, df b) {
    float p = a.h * b.h;
    float e = fmaf(a.h, b.h, -p);   // exact product tail (FMA EFT)
    e = fmaf(a.h, b.l, e);
    e = fmaf(a.l, b.h, e);
    return qts(p, e);
}
// exact scale by power of two
__device__ __forceinline__ df dscale2(df a, float p2) { return mkdf(a.h * p2, a.l * p2); }
// exact doubling
__device__ __forceinline__ df ddbl(df a) { return mkdf(a.h * 2.0f, a.l * 2.0f); }

// df reciprocal: fp32 seed + one extended Newton step -> ~1e-14 rel err
__device__ __forceinline__ df drecip(df b) {
    float y = 1.0f / b.h;
    float r = fmaf(b.h, y, -1.0f);  // exact residual of hi product
    r = fmaf(b.l, y, r);
    float dy = -y * r;
    return qts(y, dy);
}

// compile-time split of a double constant into a df (folded by nvcc)
#define DF_CONST(c) mkdf((float)(c), (float)((c) - (double)(float)(c)))

// ============================================================================
// Kernel: one thread per 3x3 matrix.
// A = sum v_k E_k  (exactly traceless, sl(3)) built EXACTLY in df via two_sum.
// Scaling-and-squaring, but all polynomial work reduced via Cayley-Hamilton:
//   T^3 = p T + q I,  p = tr(T^2)/2, q = det(T)
// exp(T) tracked as (a0, a1, a2) coefficients of a0 I + a1 T + a2 T^2;
// Taylor deg-12 Horner and all squarings are scalar df ops in that space.
// One df 3x3 matmul (T^2) + one reconstruction + normalize by H22.
// ============================================================================
__global__ __launch_bounds__(256)
void lie_expm_kernel(const float* __restrict__ v, float* __restrict__ out, int B) {
    int i = blockIdx.x * blockDim.x + threadIdx.x;
    if (i >= B) return;

    const float4* vp = reinterpret_cast<const float4*>(v + (size_t)i * 8);
    float4 lo4 = vp[0];
    float4 hi4 = vp[1];
    float v0 = lo4.x, v1 = lo4.y, v2 = lo4.z, v3 = lo4.w;
    float v4 = hi4.x, v5 = hi4.y, v6 = hi4.z, v7 = hi4.w;

    // A built exactly in df (two-term sums are error-free via two_sum)
    df T[9];
    T[0] = ts(v3,  v4);          // A00
    T[1] = ts(v5, -v2);          // A01
    T[2] = mkdf(v0, 0.0f);       // A02
    T[3] = ts(v2,  v5);          // A10
    T[4] = ts(v3, -v4);          // A11
    T[5] = mkdf(v1, 0.0f);       // A12
    T[6] = mkdf(v6, 0.0f);       // A20
    T[7] = mkdf(v7, 0.0f);       // A21
    T[8] = mkdf(-2.0f * v3, 0.0f); // A22 (exact)

    // inf-norm (fp32 on hi parts; tiny underestimate irrelevant)
    float r0 = fabsf(T[0].h) + fabsf(T[1].h) + fabsf(T[2].h);
    float r1 = fabsf(T[3].h) + fabsf(T[4].h) + fabsf(T[5].h);
    float r2 = fabsf(T[6].h) + fabsf(T[7].h) + fabsf(T[8].h);
    float nrm = fmaxf(r0, fmaxf(r1, r2));

    int s = 0;
    if (nrm > 0.5f) {
        s = (int)ceilf(log2f(nrm)) + 1;
        if (s < 0) s = 0;
        if (s > 30) s = 30;
    }
    float sc = __uint_as_float((uint32_t)(127 - s) << 23);  // exact 2^-s

#pragma unroll
    for (int k = 0; k < 9; k++) T[k] = dscale2(T[k], sc);

    // T2 = T*T in df (the single df matmul)
    df T2[9];
#pragma unroll
    for (int r = 0; r < 3; r++) {
#pragma unroll
        for (int c = 0; c < 3; c++) {
            df acc = dmul(T[r * 3 + 0], T[0 * 3 + c]);
            acc = dadd(acc, dmul(T[r * 3 + 1], T[1 * 3 + c]));
            acc = dadd(acc, dmul(T[r * 3 + 2], T[2 * 3 + c]));
            T2[r * 3 + c] = acc;
        }
    }

    // p = tr(T^2)/2 (exact halving), q = det(T)
    df p = dscale2(dadd(dadd(T2[0], T2[4]), T2[8]), 0.5f);
    df m0 = dsub(dmul(T[4], T[8]), dmul(T[5], T[7]));
    df m1 = dsub(dmul(T[3], T[8]), dmul(T[5], T[6]));
    df m2 = dsub(dmul(T[3], T[7]), dmul(T[4], T[6]));
    df q  = dadd(dsub(dmul(T[0], m0), dmul(T[1], m1)), dmul(T[2], m2));

    // Taylor deg-12 coefficients 1/k! as df constants (compile-time split)
    const df C0  = DF_CONST(1.0);
    const df C1  = DF_CONST(1.0);
    const df C2  = DF_CONST(0.5);
    const df C3  = DF_CONST(1.0 / 6.0);
    const df C4  = DF_CONST(1.0 / 24.0);
    const df C5  = DF_CONST(1.0 / 120.0);
    const df C6  = DF_CONST(1.0 / 720.0);
    const df C7  = DF_CONST(1.0 / 5040.0);
    const df C8  = DF_CONST(1.0 / 40320.0);
    const df C9  = DF_CONST(1.0 / 362880.0);
    const df C10 = DF_CONST(1.0 / 3628800.0);
    const df C11 = DF_CONST(1.0 / 39916800.0);
    const df C12 = DF_CONST(1.0 / 479001600.0);

    // Horner in the Cayley-Hamilton reduced space.
    // State P = a0 + a1*L + a2*L^2; step: P <- L*P + c_k with
    //   L*P = a2*q + (a0 + a2*p) L + a1 L^2
    df a0 = C10, a1 = C11, a2 = C12;   // peeled top (a2 zero-mults skipped)
    const df CK[10] = { C9, C8, C7, C6, C5, C4, C3, C2, C1, C0 };
#pragma unroll
    for (int k = 0; k < 10; k++) {
        df n0 = dadd(dmul(a2, q), CK[k]);
        df n1 = dadd(a0, dmul(a2, p));
        a2 = a1;
        a1 = n1;
        a0 = n0;
    }

    // s squarings in coefficient space:
    // (a0 + a1 L + a2 L^2)^2 mod (L^3 - pL - q)
    for (int it = 0; it < s; it++) {
        df s00 = dmul(a0, a0);
        df s11 = dmul(a1, a1);
        df s22 = dmul(a2, a2);
        df s01 = dmul(a0, a1);
        df s02 = dmul(a0, a2);
        df s12 = dmul(a1, a2);
        df t12 = ddbl(s12);
        df b0 = dadd(s00, dmul(t12, q));
        df b1 = dadd(dadd(ddbl(s01), dmul(t12, p)), dmul(s22, q));
        df b2 = dadd(dadd(s11, ddbl(s02)), dmul(s22, p));
        a0 = b0; a1 = b1; a2 = b2;
    }

    // Reconstruct H = a0 I + a1 T + a2 T^2
    df H[9];
#pragma unroll
    for (int k = 0; k < 9; k++) {
        df e = dadd(dmul(a1, T[k]), dmul(a2, T2[k]));
        H[k] = e;
    }
    H[0] = dadd(H[0], a0);
    H[4] = dadd(H[4], a0);
    H[8] = dadd(H[8], a0);

    // Homogeneous normalization by H22, in df (this is the critical division)
    df inv = drecip(H[8]);
    float* o = out + (size_t)i * 9;
#pragma unroll
    for (int k = 0; k < 9; k++) {
        df r = dmul(H[k], inv);
        o[k] = r.h;
    }
}

extern "C" void kernel_launch(void* const* d_in, const int* in_sizes, int n_in,
                              void* d_out, int out_size) {
    const float* v = (const float*)d_in[0];
    float* out = (float*)d_out;
    int B = in_sizes[0] / 8;
    int threads = 256;
    int blocks = (B + threads - 1) / threads;
    lie_expm_kernel<<<blocks, threads>>>(v, out, B);
}

// round 4
// speedup vs baseline: 1.0935x; 1.0935x over previous
#include <cuda_runtime.h>
#include <cuda_bf16.h>
#include <cstdint>

typedef unsigned long long u64;

// ============================================================================
// Packed f32x2 primitives (sm_103a). Two independent fp32 lanes per register
// pair; one instruction per op. Subtraction via fma(b,-1,a) (exact).
// Negate/abs on the ALU pipe via 64-bit integer ops.
// ============================================================================
__device__ __forceinline__ u64 PK(float a, float b) {
    return ((u64)__float_as_uint(b) << 32) | (u64)__float_as_uint(a);
}
__device__ __forceinline__ float LO(u64 p) { return __uint_as_float((unsigned)p); }
__device__ __forceinline__ float HI(u64 p) { return __uint_as_float((unsigned)(p >> 32)); }

__device__ __forceinline__ u64 ADD2(u64 a, u64 b) {
    u64 r; asm("add.rn.f32x2 %0,%1,%2;" : "=l"(r) : "l"(a), "l"(b)); return r;
}
__device__ __forceinline__ u64 MUL2(u64 a, u64 b) {
    u64 r; asm("mul.rn.f32x2 %0,%1,%2;" : "=l"(r) : "l"(a), "l"(b)); return r;
}
__device__ __forceinline__ u64 FMA2(u64 a, u64 b, u64 c) {
    u64 r; asm("fma.rn.f32x2 %0,%1,%2,%3;" : "=l"(r) : "l"(a), "l"(b), "l"(c)); return r;
}
__device__ __forceinline__ u64 NEG2(u64 a) { return a ^ 0x8000000080000000ULL; }
__device__ __forceinline__ u64 ABS2(u64 a) { return a & 0x7FFFFFFF7FFFFFFFULL; }
// a - b, exact single rounding: fma(b, -1, a)
__device__ __forceinline__ u64 SUB2(u64 a, u64 b) {
    return FMA2(b, 0xBF800000BF800000ULL, a);
}

// ============================================================================
// Renormalized double-float on packed lanes (identical numerics to the
// R2-proven scalar version: every op ends with quick_two_sum, so |l|<=eps|h|).
// ============================================================================
struct dd { u64 h, l; };
__device__ __forceinline__ dd mkdd(u64 h, u64 l) { dd r; r.h = h; r.l = l; return r; }

// exact two_sum of two packed singles -> normalized dd
__device__ __forceinline__ dd dd_ts(u64 a, u64 b) {
    u64 s  = ADD2(a, b);
    u64 bb = SUB2(s, a);
    u64 e  = ADD2(SUB2(a, SUB2(s, bb)), SUB2(b, bb));
    return mkdd(s, e);
}
__device__ __forceinline__ dd dadd(dd A, dd B) {
    u64 s  = ADD2(A.h, B.h);
    u64 bb = SUB2(s, A.h);
    u64 e  = ADD2(SUB2(A.h, SUB2(s, bb)), SUB2(B.h, bb));  // exact residual
    u64 t  = ADD2(e, ADD2(A.l, B.l));
    u64 hh = ADD2(s, t);                                    // qts renorm
    u64 ll = SUB2(t, SUB2(hh, s));
    return mkdd(hh, ll);
}
__device__ __forceinline__ dd dneg(dd A) { return mkdd(NEG2(A.h), NEG2(A.l)); }
__device__ __forceinline__ dd dsub(dd A, dd B) { return dadd(A, dneg(B)); }
__device__ __forceinline__ dd dmul(dd A, dd B) {
    u64 p = MUL2(A.h, B.h);
    u64 e = FMA2(A.h, B.h, NEG2(p));   // exact product tail
    e = FMA2(A.h, B.l, e);
    e = FMA2(A.l, B.h, e);
    u64 hh = ADD2(p, e);               // qts renorm
    u64 ll = SUB2(e, SUB2(hh, p));
    return mkdd(hh, ll);
}
// product collapsed straight to packed float (for final outputs)
__device__ __forceinline__ u64 dmul_f(dd A, dd B) {
    u64 p = MUL2(A.h, B.h);
    u64 e = FMA2(A.h, B.h, NEG2(p));
    e = FMA2(A.h, B.l, e);
    e = FMA2(A.l, B.h, e);
    return ADD2(p, e);
}
__device__ __forceinline__ dd dscale(dd A, u64 p2) {   // exact power-of-two scale
    return mkdd(MUL2(A.h, p2), MUL2(A.l, p2));
}
__device__ __forceinline__ dd ddbl(dd A) { return mkdd(ADD2(A.h, A.h), ADD2(A.l, A.l)); }
// reciprocal: per-lane fp32 seed + compensated Newton (done once)
__device__ __forceinline__ dd drecip(dd B) {
    float bh0 = LO(B.h), bh1 = HI(B.h), bl0 = LO(B.l), bl1 = HI(B.l);
    float y0 = 1.0f / bh0, y1 = 1.0f / bh1;
    float r0 = fmaf(bh0, y0, -1.0f); r0 = fmaf(bl0, y0, r0);
    float r1 = fmaf(bh1, y1, -1.0f); r1 = fmaf(bl1, y1, r1);
    return mkdd(PK(y0, y1), PK(-y0 * r0, -y1 * r1));
}
// dd constant, same value in both lanes
#define DDC(x) mkdd(PK((float)(x), (float)(x)), \
                    PK((float)((x) - (double)(float)(x)), (float)((x) - (double)(float)(x))))

// ============================================================================
// One thread = TWO 3x3 matrices (packed lanes).
// A traceless; Cayley-Hamilton: T^3 = pT + qI, p = tr(T^2)/2, q = det(T).
// exp tracked as (a0,a1,a2) of a0 I + a1 T + a2 T^2. theta=1, deg-13 Taylor,
// warp-uniform s, squarings in coefficient space.
// H = a0 I + T*(a1 I + a2 T) formed only at the end; normalize by H22.
// ============================================================================
__global__ __launch_bounds__(256)
void lie_expm_kernel(const float* __restrict__ v, float* __restrict__ out, int B) {
    int i = blockIdx.x * blockDim.x + threadIdx.x;
    int B2 = (B + 1) >> 1;
    if (i >= B2) return;
    int i0 = 2 * i;
    int i1 = min(2 * i + 1, B - 1);
    bool w1 = (2 * i + 1) < B;

    const float4* vp0 = reinterpret_cast<const float4*>(v + (size_t)i0 * 8);
    const float4* vp1 = reinterpret_cast<const float4*>(v + (size_t)i1 * 8);
    float4 x0 = vp0[0], x1 = vp0[1];
    float4 y0 = vp1[0], y1 = vp1[1];

    u64 V0 = PK(x0.x, y0.x), V1 = PK(x0.y, y0.y), V2 = PK(x0.z, y0.z), V3 = PK(x0.w, y0.w);
    u64 V4 = PK(x1.x, y1.x), V5 = PK(x1.y, y1.y), V6 = PK(x1.z, y1.z), V7 = PK(x1.w, y1.w);

    dd T[9];
    T[0] = dd_ts(V3, V4);
    T[1] = dd_ts(V5, NEG2(V2));
    T[2] = mkdd(V0, 0);
    T[3] = dd_ts(V2, V5);
    T[4] = dd_ts(V3, NEG2(V4));
    T[5] = mkdd(V1, 0);
    T[6] = mkdd(V6, 0);
    T[7] = mkdd(V7, 0);
    T[8] = mkdd(MUL2(V3, PK(-2.0f, -2.0f)), 0);

    // inf-norm over both lanes
    u64 r0 = ADD2(ADD2(ABS2(T[0].h), ABS2(T[1].h)), ABS2(T[2].h));
    u64 r1 = ADD2(ADD2(ABS2(T[3].h), ABS2(T[4].h)), ABS2(T[5].h));
    u64 r2 = ADD2(ADD2(ABS2(T[6].h), ABS2(T[7].h)), ABS2(T[8].h));
    float n = fmaxf(fmaxf(fmaxf(LO(r0), HI(r0)), fmaxf(LO(r1), HI(r1))),
                    fmaxf(LO(r2), HI(r2)));

    // warp-uniform scaling count (theta = 1)
    int mx = __reduce_max_sync(0xffffffffu, __float_as_int(n));
    float nw = __int_as_float(mx);
    int s = 0;
    if (nw > 1.0f) {
        s = (int)ceilf(log2f(nw));
        s = min(max(s, 0), 30);
    }
    uint32_t scb = (uint32_t)(127 - s) << 23;   // exact 2^-s
    u64 sc = ((u64)scb << 32) | scb;
#pragma unroll
    for (int k = 0; k < 9; k++) T[k] = dscale(T[k], sc);

    // p = tr(T^2)/2 = (T0^2+T4^2+T8^2)/2 + (T1*T3 + T2*T6 + T5*T7)
    dd tdiag = dadd(dadd(dmul(T[0], T[0]), dmul(T[4], T[4])), dmul(T[8], T[8]));
    dd toff  = dadd(dadd(dmul(T[1], T[3]), dmul(T[2], T[6])), dmul(T[5], T[7]));
    dd p = dadd(dscale(tdiag, PK(0.5f, 0.5f)), toff);

    // q = det(T)
    dd m0 = dsub(dmul(T[4], T[8]), dmul(T[5], T[7]));
    dd m1 = dsub(dmul(T[3], T[8]), dmul(T[5], T[6]));
    dd m2 = dsub(dmul(T[3], T[7]), dmul(T[4], T[6]));
    dd q  = dadd(dsub(dmul(T[0], m0), dmul(T[1], m1)), dmul(T[2], m2));

    // deg-13 Taylor Horner in Cayley-Hamilton reduced space
    dd a0 = DDC(1.0 / 39916800.0);          // C11
    dd a1 = DDC(1.0 / 479001600.0);         // C12
    dd a2 = DDC(1.0 / 6227020800.0);        // C13
    const dd CK[11] = {
        DDC(1.0 / 3628800.0), DDC(1.0 / 362880.0), DDC(1.0 / 40320.0),
        DDC(1.0 / 5040.0),    DDC(1.0 / 720.0),    DDC(1.0 / 120.0),
        DDC(1.0 / 24.0),      DDC(1.0 / 6.0),      DDC(0.5),
        DDC(1.0),             DDC(1.0)
    };
#pragma unroll
    for (int k = 0; k < 11; k++) {
        dd n0 = dadd(dmul(a2, q), CK[k]);
        dd n1 = dadd(a0, dmul(a2, p));
        a2 = a1;
        a1 = n1;
        a0 = n0;
    }

    // s squarings in coefficient space: (a0+a1 L+a2 L^2)^2 mod (L^3 - pL - q)
    dd q2 = ddbl(q), pp2 = ddbl(p);
    for (int it = 0; it < s; it++) {
        dd s00 = dmul(a0, a0);
        dd s11 = dmul(a1, a1);
        dd s22 = dmul(a2, a2);
        dd s01 = dmul(a0, a1);
        dd s02 = dmul(a0, a2);
        dd s12 = dmul(a1, a2);
        dd b0 = dadd(s00, dmul(s12, q2));
        dd b1 = dadd(dadd(ddbl(s01), dmul(s12, pp2)), dmul(s22, q));
        dd b2 = dadd(dadd(s11, ddbl(s02)), dmul(s22, p));
        a0 = b0; a1 = b1; a2 = b2;
    }

    // M = a1 I + a2 T
    dd M[9];
#pragma unroll
    for (int k = 0; k < 9; k++) M[k] = dmul(a2, T[k]);
    M[0] = dadd(M[0], a1);
    M[4] = dadd(M[4], a1);
    M[8] = dadd(M[8], a1);

    // H22 first (row2 . col2 + a0), then its reciprocal
    dd W8 = dadd(dadd(dmul(T[6], M[2]), dmul(T[7], M[5])), dmul(T[8], M[8]));
    W8 = dadd(W8, a0);
    dd inv = drecip(W8);

    // Remaining 8 entries of H = a0 I + T*M, each scaled by 1/H22
    float h0[9], h1[9];
#pragma unroll
    for (int r = 0; r < 3; r++) {
#pragma unroll
        for (int c = 0; c < 3; c++) {
            int k = 3 * r + c;
            if (k == 8) continue;
            dd W = dadd(dadd(dmul(T[3 * r], M[c]), dmul(T[3 * r + 1], M[3 + c])),
                        dmul(T[3 * r + 2], M[6 + c]));
            if (r == c) W = dadd(W, a0);
            u64 val = dmul_f(W, inv);
            h0[k] = LO(val);
            h1[k] = HI(val);
        }
    }
    h0[8] = 1.0f;
    h1[8] = 1.0f;

    // 9 float2 stores covering both items (72B, 8B-aligned)
    float2* o2 = reinterpret_cast<float2*>(out + (size_t)i0 * 9);
    o2[0] = make_float2(h0[0], h0[1]);
    o2[1] = make_float2(h0[2], h0[3]);
    o2[2] = make_float2(h0[4], h0[5]);
    o2[3] = make_float2(h0[6], h0[7]);
    if (w1) {
        o2[4] = make_float2(h0[8], h1[0]);
        o2[5] = make_float2(h1[1], h1[2]);
        o2[6] = make_float2(h1[3], h1[4]);
        o2[7] = make_float2(h1[5], h1[6]);
        o2[8] = make_float2(h1[7], h1[8]);
    } else {
        out[(size_t)i0 * 9 + 8] = h0[8];
    }
}

extern "C" void kernel_launch(void* const* d_in, const int* in_sizes, int n_in,
                              void* d_out, int out_size) {
    const float* v = (const float*)d_in[0];
    float* out = (float*)d_out;
    int B = in_sizes[0] / 8;
    int B2 = (B + 1) / 2;
    int threads = 256;
    int blocks = (B2 + threads - 1) / threads;
    lie_expm_kernel<<<blocks, threads>>>(v, out, B);
}

// round 5
// speedup vs baseline: 1.3706x; 1.2533x over previous
#include <cuda_runtime.h>
#include <cuda_bf16.h>
#include <cstdint>

typedef unsigned long long u64;

// ============================================================================
// Packed f32x2 primitives (sm_103a).
// ============================================================================
__device__ __forceinline__ u64 PK(float a, float b) {
    return ((u64)__float_as_uint(b) << 32) | (u64)__float_as_uint(a);
}
__device__ __forceinline__ float LO(u64 p) { return __uint_as_float((unsigned)p); }
__device__ __forceinline__ float HI(u64 p) { return __uint_as_float((unsigned)(p >> 32)); }

__device__ __forceinline__ u64 ADD2(u64 a, u64 b) {
    u64 r; asm("add.rn.f32x2 %0,%1,%2;" : "=l"(r) : "l"(a), "l"(b)); return r;
}
__device__ __forceinline__ u64 MUL2(u64 a, u64 b) {
    u64 r; asm("mul.rn.f32x2 %0,%1,%2;" : "=l"(r) : "l"(a), "l"(b)); return r;
}
__device__ __forceinline__ u64 FMA2(u64 a, u64 b, u64 c) {
    u64 r; asm("fma.rn.f32x2 %0,%1,%2,%3;" : "=l"(r) : "l"(a), "l"(b), "l"(c)); return r;
}
__device__ __forceinline__ u64 NEG2(u64 a) { return a ^ 0x8000000080000000ULL; }
__device__ __forceinline__ u64 ABS2(u64 a) { return a & 0x7FFFFFFF7FFFFFFFULL; }
__device__ __forceinline__ u64 SUB2(u64 a, u64 b) {   // exact: fma(b,-1,a)
    return FMA2(b, 0xBF800000BF800000ULL, a);
}

// ============================================================================
// double-float on packed lanes.
// dadd: full two_sum + renorm (cancellation-safe, R2-proven).
// dadd_nr: keeps exact residual, skips final renorm — ONLY for chains that
//          terminate in the fp32 collapse (never feeds a dmul).
// dmul_s: sloppy product (|l|<=3eps|h|) — safe as input to any dd op.
// ============================================================================
struct dd { u64 h, l; };
__device__ __forceinline__ dd mkdd(u64 h, u64 l) { dd r; r.h = h; r.l = l; return r; }

__device__ __forceinline__ dd dd_ts(u64 a, u64 b) {   // exact two_sum
    u64 s  = ADD2(a, b);
    u64 bb = SUB2(s, a);
    u64 e  = ADD2(SUB2(a, SUB2(s, bb)), SUB2(b, bb));
    return mkdd(s, e);
}
__device__ __forceinline__ dd dadd(dd A, dd B) {      // full (11 ops)
    u64 s  = ADD2(A.h, B.h);
    u64 bb = SUB2(s, A.h);
    u64 e  = ADD2(SUB2(A.h, SUB2(s, bb)), SUB2(B.h, bb));
    u64 t  = ADD2(e, ADD2(A.l, B.l));
    u64 hh = ADD2(s, t);
    u64 ll = SUB2(t, SUB2(hh, s));
    return mkdd(hh, ll);
}
__device__ __forceinline__ dd dadd_nr(dd A, dd B) {   // no final renorm (8 ops)
    u64 s  = ADD2(A.h, B.h);
    u64 bb = SUB2(s, A.h);
    u64 e  = ADD2(SUB2(A.h, SUB2(s, bb)), SUB2(B.h, bb));
    u64 t  = ADD2(e, ADD2(A.l, B.l));
    return mkdd(s, t);
}
__device__ __forceinline__ dd dneg(dd A) { return mkdd(NEG2(A.h), NEG2(A.l)); }
__device__ __forceinline__ dd dsub(dd A, dd B) { return dadd(A, dneg(B)); }

__device__ __forceinline__ dd dmul_s(dd A, dd B) {    // sloppy (4 fp ops)
    u64 p = MUL2(A.h, B.h);
    u64 e = FMA2(A.h, B.h, NEG2(p));
    e = FMA2(A.h, B.l, e);
    e = FMA2(A.l, B.h, e);
    return mkdd(p, e);
}
__device__ __forceinline__ dd dmul_bl0(dd A, u64 Bh) { // B.l == 0 (3 ops)
    u64 p = MUL2(A.h, Bh);
    u64 e = FMA2(A.h, Bh, NEG2(p));
    e = FMA2(A.l, Bh, e);
    return mkdd(p, e);
}
__device__ __forceinline__ dd dmul_al0(u64 Ah, dd B) { // A.l == 0 (3 ops)
    u64 p = MUL2(Ah, B.h);
    u64 e = FMA2(Ah, B.h, NEG2(p));
    e = FMA2(Ah, B.l, e);
    return mkdd(p, e);
}
__device__ __forceinline__ dd dmul_exact(u64 Ah, u64 Bh) { // exact (2 ops)
    u64 p = MUL2(Ah, Bh);
    u64 e = FMA2(Ah, Bh, NEG2(p));
    return mkdd(p, e);
}
__device__ __forceinline__ dd dscale(dd A, u64 p2) {
    return mkdd(MUL2(A.h, p2), MUL2(A.l, p2));
}
__device__ __forceinline__ dd ddbl(dd A) { return mkdd(ADD2(A.h, A.h), ADD2(A.l, A.l)); }
__device__ __forceinline__ dd drecip(dd B) {
    float bh0 = LO(B.h), bh1 = HI(B.h), bl0 = LO(B.l), bl1 = HI(B.l);
    float y0 = 1.0f / bh0, y1 = 1.0f / bh1;
    float r0 = fmaf(bh0, y0, -1.0f); r0 = fmaf(bl0, y0, r0);
    float r1 = fmaf(bh1, y1, -1.0f); r1 = fmaf(bl1, y1, r1);
    return mkdd(PK(y0, y1), PK(-y0 * r0, -y1 * r1));
}
__device__ __forceinline__ u64 collapse(dd A) { return ADD2(A.h, A.l); }
#define DDC(x) mkdd(PK((float)(x), (float)(x)), \
                    PK((float)((x) - (double)(float)(x)), (float)((x) - (double)(float)(x))))

// ============================================================================
// One thread = TWO matrices. Cayley-Hamilton reduced expm (see R2/R3 notes).
// T0,T1,T3,T4 are full dd; T2,T5,T6,T7,T8 have exactly-zero low words.
// ============================================================================
__global__ __launch_bounds__(256)
void lie_expm_kernel(const float* __restrict__ v, float* __restrict__ out, int B) {
    int i = blockIdx.x * blockDim.x + threadIdx.x;
    int B2 = (B + 1) >> 1;
    if (i >= B2) return;
    int i0 = 2 * i;
    int i1 = min(2 * i + 1, B - 1);
    bool w1 = (2 * i + 1) < B;

    const float4* vp0 = reinterpret_cast<const float4*>(v + (size_t)i0 * 8);
    const float4* vp1 = reinterpret_cast<const float4*>(v + (size_t)i1 * 8);
    float4 x0 = vp0[0], x1 = vp0[1];
    float4 y0 = vp1[0], y1 = vp1[1];

    u64 V0 = PK(x0.x, y0.x), V1 = PK(x0.y, y0.y), V2 = PK(x0.z, y0.z), V3 = PK(x0.w, y0.w);
    u64 V4 = PK(x1.x, y1.x), V5 = PK(x1.y, y1.y), V6 = PK(x1.z, y1.z), V7 = PK(x1.w, y1.w);

    dd T0 = dd_ts(V3, V4);
    dd T1 = dd_ts(V5, NEG2(V2));
    dd T3 = dd_ts(V2, V5);
    dd T4 = dd_ts(V3, NEG2(V4));
    u64 T2 = V0, T5 = V1, T6 = V6, T7 = V7;
    u64 T8 = MUL2(V3, PK(-2.0f, -2.0f));   // exact

    // inf-norm over both lanes
    u64 r0 = ADD2(ADD2(ABS2(T0.h), ABS2(T1.h)), ABS2(T2));
    u64 r1 = ADD2(ADD2(ABS2(T3.h), ABS2(T4.h)), ABS2(T5));
    u64 r2 = ADD2(ADD2(ABS2(T6), ABS2(T7)), ABS2(T8));
    float n = fmaxf(fmaxf(fmaxf(LO(r0), HI(r0)), fmaxf(LO(r1), HI(r1))),
                    fmaxf(LO(r2), HI(r2)));

    // warp-uniform scaling count (theta = 1)
    int mx = __reduce_max_sync(0xffffffffu, __float_as_int(n));
    float nw = __int_as_float(mx);
    int s = 0;
    if (nw > 1.0f) {
        s = (int)ceilf(log2f(nw));
        s = min(max(s, 0), 30);
    }
    uint32_t scb = (uint32_t)(127 - s) << 23;   // exact 2^-s
    u64 sc = ((u64)scb << 32) | scb;
    T0 = dscale(T0, sc); T1 = dscale(T1, sc); T3 = dscale(T3, sc); T4 = dscale(T4, sc);
    T2 = MUL2(T2, sc); T5 = MUL2(T5, sc); T6 = MUL2(T6, sc); T7 = MUL2(T7, sc);
    T8 = MUL2(T8, sc);

    // p = tr(T^2)/2 = (T0^2+T4^2+T8^2)/2 + (T1*T3 + T2*T6 + T5*T7)
    dd d88 = dmul_exact(T8, T8);
    dd d57 = dmul_exact(T5, T7);
    dd tdiag = dadd(dadd(dmul_s(T0, T0), dmul_s(T4, T4)), d88);
    dd toff  = dadd(dadd(dmul_s(T1, T3), dmul_exact(T2, T6)), d57);
    dd p = dadd(dscale(tdiag, PK(0.5f, 0.5f)), toff);

    // q = det(T)
    dd m0 = dsub(dmul_bl0(T4, T8), d57);
    dd m1 = dsub(dmul_bl0(T3, T8), dmul_exact(T5, T6));
    dd m2 = dsub(dmul_bl0(T3, T7), dmul_bl0(T4, T6));
    dd q  = dadd(dsub(dmul_s(T0, m0), dmul_s(T1, m1)), dmul_al0(T2, m2));

    // deg-13 Taylor Horner in Cayley-Hamilton reduced space
    dd a0 = DDC(1.0 / 39916800.0);
    dd a1 = DDC(1.0 / 479001600.0);
    dd a2 = DDC(1.0 / 6227020800.0);
    const dd CK[11] = {
        DDC(1.0 / 3628800.0), DDC(1.0 / 362880.0), DDC(1.0 / 40320.0),
        DDC(1.0 / 5040.0),    DDC(1.0 / 720.0),    DDC(1.0 / 120.0),
        DDC(1.0 / 24.0),      DDC(1.0 / 6.0),      DDC(0.5),
        DDC(1.0),             DDC(1.0)
    };
#pragma unroll
    for (int k = 0; k < 11; k++) {
        dd n0 = dadd(dmul_s(a2, q), CK[k]);
        dd n1 = dadd(a0, dmul_s(a2, p));
        a2 = a1;
        a1 = n1;
        a0 = n0;
    }

    // s squarings: (a0 + a1 L + a2 L^2)^2 mod (L^3 - pL - q)
    dd q2 = ddbl(q), pp2 = ddbl(p);
    for (int it = 0; it < s; it++) {
        dd s00 = dmul_s(a0, a0);
        dd s11 = dmul_s(a1, a1);
        dd s22 = dmul_s(a2, a2);
        dd s01 = dmul_s(a0, a1);
        dd s02 = dmul_s(a0, a2);
        dd s12 = dmul_s(a1, a2);
        dd b0 = dadd(s00, dmul_s(s12, q2));
        dd b1 = dadd(dadd(ddbl(s01), dmul_s(s12, pp2)), dmul_s(s22, q));
        dd b2 = dadd(dadd(s11, ddbl(s02)), dmul_s(s22, p));
        a0 = b0; a1 = b1; a2 = b2;
    }

    // H22 = a0 + a1*T8 + a2*T2_22,  T2_22 = T6*T2 + T7*T5 + T8*T8
    dd t222 = dadd(dadd(dmul_exact(T6, T2), dmul_exact(T7, T5)), d88);
    dd h22  = dadd(dadd(dmul_bl0(a1, T8), dmul_s(a2, t222)), a0);
    dd inv  = drecip(h22);

    // fold 1/H22 into coefficients
    dd b0c = dmul_s(a0, inv);
    dd b1c = dmul_s(a1, inv);
    dd b2c = dmul_s(a2, inv);

    // M = b1 I + b2 T  (diag entries fully renormalized: they feed dmuls)
    dd M0 = dadd(dmul_s(b2c, T0), b1c);
    dd M1 = dmul_s(b2c, T1);
    dd M2 = dmul_bl0(b2c, T2);
    dd M3 = dmul_s(b2c, T3);
    dd M4 = dadd(dmul_s(b2c, T4), b1c);
    dd M5 = dmul_bl0(b2c, T5);
    dd M6 = dmul_bl0(b2c, T6);
    dd M7 = dmul_bl0(b2c, T7);
    dd M8 = dadd(dmul_bl0(b2c, T8), b1c);

    // H/H22 = b0 I + T*M ; entry (2,2) is exactly 1.
    u64 h[8];
    // row 0
    h[0] = collapse(dadd_nr(dadd_nr(dadd_nr(dmul_s(T0, M0), dmul_s(T1, M3)),
                                    dmul_al0(T2, M6)), b0c));
    h[1] = collapse(dadd_nr(dadd_nr(dmul_s(T0, M1), dmul_s(T1, M4)),
                            dmul_al0(T2, M7)));
    h[2] = collapse(dadd_nr(dadd_nr(dmul_s(T0, M2), dmul_s(T1, M5)),
                            dmul_al0(T2, M8)));
    // row 1
    h[3] = collapse(dadd_nr(dadd_nr(dmul_s(T3, M0), dmul_s(T4, M3)),
                            dmul_al0(T5, M6)));
    h[4] = collapse(dadd_nr(dadd_nr(dadd_nr(dmul_s(T3, M1), dmul_s(T4, M4)),
                                    dmul_al0(T5, M7)), b0c));
    h[5] = collapse(dadd_nr(dadd_nr(dmul_s(T3, M2), dmul_s(T4, M5)),
                            dmul_al0(T5, M8)));
    // row 2
    h[6] = collapse(dadd_nr(dadd_nr(dmul_al0(T6, M0), dmul_al0(T7, M3)),
                            dmul_al0(T8, M6)));
    h[7] = collapse(dadd_nr(dadd_nr(dmul_al0(T6, M1), dmul_al0(T7, M4)),
                            dmul_al0(T8, M7)));

    // stores: 9 float2 covering both items
    float2* o2 = reinterpret_cast<float2*>(out + (size_t)i0 * 9);
    o2[0] = make_float2(LO(h[0]), LO(h[1]));
    o2[1] = make_float2(LO(h[2]), LO(h[3]));
    o2[2] = make_float2(LO(h[4]), LO(h[5]));
    o2[3] = make_float2(LO(h[6]), LO(h[7]));
    if (w1) {
        o2[4] = make_float2(1.0f, HI(h[0]));
        o2[5] = make_float2(HI(h[1]), HI(h[2]));
        o2[6] = make_float2(HI(h[3]), HI(h[4]));
        o2[7] = make_float2(HI(h[5]), HI(h[6]));
        o2[8] = make_float2(HI(h[7]), 1.0f);
    } else {
        out[(size_t)i0 * 9 + 8] = 1.0f;
    }
}

extern "C" void kernel_launch(void* const* d_in, const int* in_sizes, int n_in,
                              void* d_out, int out_size) {
    const float* v = (const float*)d_in[0];
    float* out = (float*)d_out;
    int B = in_sizes[0] / 8;
    int B2 = (B + 1) / 2;
    int threads = 256;
    int blocks = (B2 + threads - 1) / threads;
    lie_expm_kernel<<<blocks, threads>>>(v, out, B);
}

// round 6
// speedup vs baseline: 1.5166x; 1.1066x over previous
#include <cuda_runtime.h>
#include <cuda_bf16.h>
#include <cstdint>

typedef unsigned long long u64;

// ============================================================================
// Packed f32x2 primitives (sm_103a).
// ============================================================================
__device__ __forceinline__ u64 PK(float a, float b) {
    return ((u64)__float_as_uint(b) << 32) | (u64)__float_as_uint(a);
}
__device__ __forceinline__ float LO(u64 p) { return __uint_as_float((unsigned)p); }
__device__ __forceinline__ float HI(u64 p) { return __uint_as_float((unsigned)(p >> 32)); }

__device__ __forceinline__ u64 ADD2(u64 a, u64 b) {
    u64 r; asm("add.rn.f32x2 %0,%1,%2;" : "=l"(r) : "l"(a), "l"(b)); return r;
}
__device__ __forceinline__ u64 MUL2(u64 a, u64 b) {
    u64 r; asm("mul.rn.f32x2 %0,%1,%2;" : "=l"(r) : "l"(a), "l"(b)); return r;
}
__device__ __forceinline__ u64 FMA2(u64 a, u64 b, u64 c) {
    u64 r; asm("fma.rn.f32x2 %0,%1,%2,%3;" : "=l"(r) : "l"(a), "l"(b), "l"(c)); return r;
}
__device__ __forceinline__ u64 NEG2(u64 a) { return a ^ 0x8000000080000000ULL; }
__device__ __forceinline__ u64 ABS2(u64 a) { return a & 0x7FFFFFFF7FFFFFFFULL; }
__device__ __forceinline__ u64 SUB2(u64 a, u64 b) {   // exact: fma(b,-1,a)
    return FMA2(b, 0xBF800000BF800000ULL, a);
}

// ============================================================================
// double-float on packed lanes.
// Invariant discipline (validated R2..R5):
//  - dmul of two UNNORMALIZED operands is forbidden (drops O(1) l*l).
//  - unnormalized x normalized dmul is eps-safe.
//  - dadd_nr keeps the exact two_sum residual (cancellation-safe) but skips
//    the final renorm; its output counts as UNNORMALIZED.
// ============================================================================
struct dd { u64 h, l; };
__device__ __forceinline__ dd mkdd(u64 h, u64 l) { dd r; r.h = h; r.l = l; return r; }

__device__ __forceinline__ dd dd_ts(u64 a, u64 b) {   // exact two_sum (normalized)
    u64 s  = ADD2(a, b);
    u64 bb = SUB2(s, a);
    u64 e  = ADD2(SUB2(a, SUB2(s, bb)), SUB2(b, bb));
    return mkdd(s, e);
}
__device__ __forceinline__ dd dadd(dd A, dd B) {      // full, renormalized (11)
    u64 s  = ADD2(A.h, B.h);
    u64 bb = SUB2(s, A.h);
    u64 e  = ADD2(SUB2(A.h, SUB2(s, bb)), SUB2(B.h, bb));
    u64 t  = ADD2(e, ADD2(A.l, B.l));
    u64 hh = ADD2(s, t);
    u64 ll = SUB2(t, SUB2(hh, s));
    return mkdd(hh, ll);
}
__device__ __forceinline__ dd dadd_nr(dd A, dd B) {   // no renorm (8)
    u64 s  = ADD2(A.h, B.h);
    u64 bb = SUB2(s, A.h);
    u64 e  = ADD2(SUB2(A.h, SUB2(s, bb)), SUB2(B.h, bb));
    u64 t  = ADD2(e, ADD2(A.l, B.l));
    return mkdd(s, t);
}
__device__ __forceinline__ dd dneg(dd A) { return mkdd(NEG2(A.h), NEG2(A.l)); }
__device__ __forceinline__ dd dsub_nr(dd A, dd B) { return dadd_nr(A, dneg(B)); }
__device__ __forceinline__ dd renorm(dd A) {          // (3)
    u64 hh = ADD2(A.h, A.l);
    u64 ll = SUB2(A.l, SUB2(hh, A.h));
    return mkdd(hh, ll);
}
__device__ __forceinline__ dd dmul_s(dd A, dd B) {    // sloppy product (4)
    u64 p = MUL2(A.h, B.h);
    u64 e = FMA2(A.h, B.h, NEG2(p));
    e = FMA2(A.h, B.l, e);
    e = FMA2(A.l, B.h, e);
    return mkdd(p, e);
}
__device__ __forceinline__ dd dmul_bl0(dd A, u64 Bh) { // B.l == 0 (3)
    u64 p = MUL2(A.h, Bh);
    u64 e = FMA2(A.h, Bh, NEG2(p));
    e = FMA2(A.l, Bh, e);
    return mkdd(p, e);
}
__device__ __forceinline__ dd dmul_al0(u64 Ah, dd B) { // A.l == 0 (3)
    u64 p = MUL2(Ah, B.h);
    u64 e = FMA2(Ah, B.h, NEG2(p));
    e = FMA2(Ah, B.l, e);
    return mkdd(p, e);
}
__device__ __forceinline__ dd dmul_exact(u64 Ah, u64 Bh) { // exact (2)
    u64 p = MUL2(Ah, Bh);
    u64 e = FMA2(Ah, Bh, NEG2(p));
    return mkdd(p, e);
}
__device__ __forceinline__ dd dscale(dd A, u64 p2) {
    return mkdd(MUL2(A.h, p2), MUL2(A.l, p2));
}
__device__ __forceinline__ dd ddbl(dd A) { return mkdd(ADD2(A.h, A.h), ADD2(A.l, A.l)); }
__device__ __forceinline__ dd drecip(dd B) {
    float bh0 = LO(B.h), bh1 = HI(B.h), bl0 = LO(B.l), bl1 = HI(B.l);
    float y0 = 1.0f / bh0, y1 = 1.0f / bh1;
    float r0 = fmaf(bh0, y0, -1.0f); r0 = fmaf(bl0, y0, r0);
    float r1 = fmaf(bh1, y1, -1.0f); r1 = fmaf(bl1, y1, r1);
    return mkdd(PK(y0, y1), PK(-y0 * r0, -y1 * r1));
}
__device__ __forceinline__ u64 collapse(dd A) { return ADD2(A.h, A.l); }
#define DDC(x) mkdd(PK((float)(x), (float)(x)), \
                    PK((float)((x) - (double)(float)(x)), (float)((x) - (double)(float)(x))))

// ============================================================================
// One thread = TWO matrices. Cayley-Hamilton reduced expm.
// ============================================================================
__global__ __launch_bounds__(128, 6)
void lie_expm_kernel(const float* __restrict__ v, float* __restrict__ out, int B) {
    int i = blockIdx.x * blockDim.x + threadIdx.x;
    int B2 = (B + 1) >> 1;
    if (i >= B2) return;
    int i0 = 2 * i;
    int i1 = min(2 * i + 1, B - 1);
    bool w1 = (2 * i + 1) < B;

    const float4* vp0 = reinterpret_cast<const float4*>(v + (size_t)i0 * 8);
    const float4* vp1 = reinterpret_cast<const float4*>(v + (size_t)i1 * 8);
    float4 x0 = vp0[0], x1 = vp0[1];
    float4 y0 = vp1[0], y1 = vp1[1];

    u64 V0 = PK(x0.x, y0.x), V1 = PK(x0.y, y0.y), V2 = PK(x0.z, y0.z), V3 = PK(x0.w, y0.w);
    u64 V4 = PK(x1.x, y1.x), V5 = PK(x1.y, y1.y), V6 = PK(x1.z, y1.z), V7 = PK(x1.w, y1.w);

    dd T0 = dd_ts(V3, V4);
    dd T1 = dd_ts(V5, NEG2(V2));
    dd T3 = dd_ts(V2, V5);
    dd T4 = dd_ts(V3, NEG2(V4));
    u64 T2 = V0, T5 = V1, T6 = V6, T7 = V7;
    u64 T8 = MUL2(V3, PK(-2.0f, -2.0f));   // exact

    // inf-norm over both lanes
    u64 r0 = ADD2(ADD2(ABS2(T0.h), ABS2(T1.h)), ABS2(T2));
    u64 r1 = ADD2(ADD2(ABS2(T3.h), ABS2(T4.h)), ABS2(T5));
    u64 r2 = ADD2(ADD2(ABS2(T6), ABS2(T7)), ABS2(T8));
    float n = fmaxf(fmaxf(fmaxf(LO(r0), HI(r0)), fmaxf(LO(r1), HI(r1))),
                    fmaxf(LO(r2), HI(r2)));

    // warp-uniform scaling count (theta = 1)
    int mx = __reduce_max_sync(0xffffffffu, __float_as_int(n));
    float nw = __int_as_float(mx);
    int s = 0;
    if (nw > 1.0f) {
        s = (int)ceilf(log2f(nw));
        s = min(max(s, 0), 30);
    }
    uint32_t scb = (uint32_t)(127 - s) << 23;   // exact 2^-s
    u64 sc = ((u64)scb << 32) | scb;
    T0 = dscale(T0, sc); T1 = dscale(T1, sc); T3 = dscale(T3, sc); T4 = dscale(T4, sc);
    T2 = MUL2(T2, sc); T5 = MUL2(T5, sc); T6 = MUL2(T6, sc); T7 = MUL2(T7, sc);
    T8 = MUL2(T8, sc);

    // p = tr(T^2)/2 ; q = det(T)  (both fully renormalized: they pair with
    // unnormalized Horner coefficients in dmul_s)
    dd d88 = dmul_exact(T8, T8);
    dd d57 = dmul_exact(T5, T7);
    dd tdiag = dadd_nr(dadd_nr(dmul_s(T0, T0), dmul_s(T4, T4)), d88);
    dd toff  = dadd_nr(dadd_nr(dmul_s(T1, T3), dmul_exact(T2, T6)), d57);
    dd p = dadd(dscale(tdiag, PK(0.5f, 0.5f)), toff);

    dd m0 = dsub_nr(dmul_bl0(T4, T8), d57);               // unnorm x norm-T: safe
    dd m1 = dsub_nr(dmul_bl0(T3, T8), dmul_exact(T5, T6));
    dd m2 = dsub_nr(dmul_bl0(T3, T7), dmul_bl0(T4, T6));
    dd q  = dadd(dadd_nr(dmul_s(T0, m0), dneg(dmul_s(T1, m1))), dmul_al0(T2, m2));

    // deg-13 Taylor Horner (coeffs unnormalized throughout; p,q normalized)
    dd a0 = DDC(1.0 / 39916800.0);
    dd a1 = DDC(1.0 / 479001600.0);
    dd a2 = DDC(1.0 / 6227020800.0);
    const dd CK[11] = {
        DDC(1.0 / 3628800.0), DDC(1.0 / 362880.0), DDC(1.0 / 40320.0),
        DDC(1.0 / 5040.0),    DDC(1.0 / 720.0),    DDC(1.0 / 120.0),
        DDC(1.0 / 24.0),      DDC(1.0 / 6.0),      DDC(0.5),
        DDC(1.0),             DDC(1.0)
    };
#pragma unroll
    for (int k = 0; k < 11; k++) {
        dd n0 = dadd_nr(dmul_s(a2, q), CK[k]);
        dd n1 = dadd_nr(a0, dmul_s(a2, p));
        a2 = a1;
        a1 = n1;
        a0 = n0;
    }
    // normalize before coefficients start multiplying EACH OTHER
    a0 = renorm(a0); a1 = renorm(a1); a2 = renorm(a2);

    // s squarings: (a0 + a1 L + a2 L^2)^2 mod (L^3 - pL - q)
    dd q2 = ddbl(q), pp2 = ddbl(p);
    for (int it = 0; it < s; it++) {
        dd s00 = dmul_s(a0, a0);
        dd s11 = dmul_s(a1, a1);
        dd s22 = dmul_s(a2, a2);
        dd s01 = dmul_s(a0, a1);
        dd s02 = dmul_s(a0, a2);
        dd s12 = dmul_s(a1, a2);
        // final add per coefficient is FULL (outputs cross-multiply next iter)
        dd b0 = dadd(s00, dmul_s(s12, q2));
        dd b1 = dadd(dadd_nr(ddbl(s01), dmul_s(s12, pp2)), dmul_s(s22, q));
        dd b2 = dadd(dadd_nr(s11, ddbl(s02)), dmul_s(s22, p));
        a0 = b0; a1 = b1; a2 = b2;
    }

    // H22 = a0 + a1*T8 + a2*T2_22,  T2_22 = T6*T2 + T7*T5 + T8*T8
    dd t222 = dadd(dadd_nr(dmul_exact(T6, T2), dmul_exact(T7, T5)), d88);
    dd h22  = dadd(dadd_nr(dmul_bl0(a1, T8), dmul_s(a2, t222)), a0);
    dd inv  = drecip(h22);

    // fold 1/H22 into coefficients (unnormalized; always paired with norm T)
    dd b0c = dmul_s(a0, inv);
    dd b1c = dmul_s(a1, inv);
    dd b2c = dmul_s(a2, inv);

    // M = b1 I + b2 T  (M entries unnormalized; consumed only vs normalized T)
    dd M0 = dadd_nr(dmul_s(b2c, T0), b1c);
    dd M1 = dmul_s(b2c, T1);
    dd M2 = dmul_bl0(b2c, T2);
    dd M3 = dmul_s(b2c, T3);
    dd M4 = dadd_nr(dmul_s(b2c, T4), b1c);
    dd M5 = dmul_bl0(b2c, T5);
    dd M6 = dmul_bl0(b2c, T6);
    dd M7 = dmul_bl0(b2c, T7);
    dd M8 = dadd_nr(dmul_bl0(b2c, T8), b1c);

    // H/H22 = b0 I + T*M ; entry (2,2) is exactly 1.
    u64 h[8];
    h[0] = collapse(dadd_nr(dadd_nr(dadd_nr(dmul_s(T0, M0), dmul_s(T1, M3)),
                                    dmul_al0(T2, M6)), b0c));
    h[1] = collapse(dadd_nr(dadd_nr(dmul_s(T0, M1), dmul_s(T1, M4)),
                            dmul_al0(T2, M7)));
    h[2] = collapse(dadd_nr(dadd_nr(dmul_s(T0, M2), dmul_s(T1, M5)),
                            dmul_al0(T2, M8)));
    h[3] = collapse(dadd_nr(dadd_nr(dmul_s(T3, M0), dmul_s(T4, M3)),
                            dmul_al0(T5, M6)));
    h[4] = collapse(dadd_nr(dadd_nr(dadd_nr(dmul_s(T3, M1), dmul_s(T4, M4)),
                                    dmul_al0(T5, M7)), b0c));
    h[5] = collapse(dadd_nr(dadd_nr(dmul_s(T3, M2), dmul_s(T4, M5)),
                            dmul_al0(T5, M8)));
    h[6] = collapse(dadd_nr(dadd_nr(dmul_al0(T6, M0), dmul_al0(T7, M3)),
                            dmul_al0(T8, M6)));
    h[7] = collapse(dadd_nr(dadd_nr(dmul_al0(T6, M1), dmul_al0(T7, M4)),
                            dmul_al0(T8, M7)));

    // stores: 9 float2 covering both items
    float2* o2 = reinterpret_cast<float2*>(out + (size_t)i0 * 9);
    o2[0] = make_float2(LO(h[0]), LO(h[1]));
    o2[1] = make_float2(LO(h[2]), LO(h[3]));
    o2[2] = make_float2(LO(h[4]), LO(h[5]));
    o2[3] = make_float2(LO(h[6]), LO(h[7]));
    if (w1) {
        o2[4] = make_float2(1.0f, HI(h[0]));
        o2[5] = make_float2(HI(h[1]), HI(h[2]));
        o2[6] = make_float2(HI(h[3]), HI(h[4]));
        o2[7] = make_float2(HI(h[5]), HI(h[6]));
        o2[8] = make_float2(HI(h[7]), 1.0f);
    } else {
        out[(size_t)i0 * 9 + 8] = 1.0f;
    }
}

extern "C" void kernel_launch(void* const* d_in, const int* in_sizes, int n_in,
                              void* d_out, int out_size) {
    const float* v = (const float*)d_in[0];
    float* out = (float*)d_out;
    int B = in_sizes[0] / 8;
    int B2 = (B + 1) / 2;
    int threads = 128;
    int blocks = (B2 + threads - 1) / threads;
    lie_expm_kernel<<<blocks, threads>>>(v, out, B);
}